// round 1
// baseline (speedup 1.0000x reference)
#include <cuda_runtime.h>
#include <math.h>

// Problem constants (fixed by reference)
#define DIM    64
#define HID    128
#define NSTEPS 100
#define BATCH  8192
#define RPC    64                  // rows per CTA
#define NCTA   (BATCH / RPC)       // 128
#define NTHR   256
#define DT_F   0.01f

// Shared memory layout (floats):
//  Wd1 8192 | Wd2 8192 | Wg1 8192 | Wg2 8192 | bd1 128 | bd2 64 | bg1 128 | bg2 64
//  X 4096 | H 8192 | F 4096   => 49,536 floats = 198,144 bytes
#define SMEM_FLOATS (4*DIM*HID + 2*HID + 2*DIM + RPC*DIM + RPC*HID + RPC*DIM)

// Layer 1: H[r][c] = tanh( sum_k X[r][k] * W[k][c] + b[c] )
// Thread (rg = tid>>5, ci = tid&31) computes rows rg*8..rg*8+7, cols ci+32*{0..3}.
__device__ __forceinline__ void layer1(const float* __restrict__ sX,
                                       const float* __restrict__ sW,
                                       const float* __restrict__ sb,
                                       float* __restrict__ sH,
                                       int rg, int ci)
{
    float acc[8][4];
#pragma unroll
    for (int r = 0; r < 8; r++)
#pragma unroll
        for (int m = 0; m < 4; m++) acc[r][m] = 0.0f;

#pragma unroll 8
    for (int k = 0; k < DIM; k++) {
        float xv[8], wv[4];
#pragma unroll
        for (int r = 0; r < 8; r++) xv[r] = sX[(rg * 8 + r) * DIM + k];   // broadcast
#pragma unroll
        for (int m = 0; m < 4; m++) wv[m] = sW[k * HID + ci + 32 * m];    // stride-1
#pragma unroll
        for (int r = 0; r < 8; r++)
#pragma unroll
            for (int m = 0; m < 4; m++) acc[r][m] = fmaf(xv[r], wv[m], acc[r][m]);
    }

#pragma unroll
    for (int m = 0; m < 4; m++) {
        const int c = ci + 32 * m;
        const float b = sb[c];
#pragma unroll
        for (int r = 0; r < 8; r++)
            sH[(rg * 8 + r) * HID + c] = tanhf(acc[r][m] + b);
    }
}

__global__ __launch_bounds__(NTHR, 1)
void sde_persistent_kernel(const float* __restrict__ x0,
                           const float* __restrict__ noise,
                           const float* __restrict__ Wd1, const float* __restrict__ bd1,
                           const float* __restrict__ Wd2, const float* __restrict__ bd2,
                           const float* __restrict__ Wg1, const float* __restrict__ bg1,
                           const float* __restrict__ Wg2, const float* __restrict__ bg2,
                           float* __restrict__ out)
{
    extern __shared__ float sm[];
    float* sWd1 = sm;                    // [DIM][HID]
    float* sWd2 = sWd1 + DIM * HID;      // [HID][DIM]
    float* sWg1 = sWd2 + HID * DIM;      // [DIM][HID]
    float* sWg2 = sWg1 + DIM * HID;      // [HID][DIM]
    float* sbd1 = sWg2 + HID * DIM;      // [HID]
    float* sbd2 = sbd1 + HID;            // [DIM]
    float* sbg1 = sbd2 + DIM;            // [HID]
    float* sbg2 = sbg1 + HID;            // [DIM]
    float* sX   = sbg2 + DIM;            // [RPC][DIM]
    float* sH   = sX + RPC * DIM;        // [RPC][HID]
    float* sF   = sH + RPC * HID;        // [RPC][DIM]

    const int tid  = threadIdx.x;
    const int row0 = blockIdx.x * RPC;

    // Stage weights + biases into SMEM (reused 100 steps)
    for (int i = tid; i < DIM * HID; i += NTHR) {
        sWd1[i] = Wd1[i];
        sWd2[i] = Wd2[i];
        sWg1[i] = Wg1[i];
        sWg2[i] = Wg2[i];
    }
    for (int i = tid; i < HID; i += NTHR) { sbd1[i] = bd1[i]; sbg1[i] = bg1[i]; }
    for (int i = tid; i < DIM; i += NTHR) { sbd2[i] = bd2[i]; sbg2[i] = bg2[i]; }

    // Load x0 tile; also emit out[0] = x0
    for (int i = tid; i < RPC * DIM; i += NTHR) {
        float v = x0[row0 * DIM + i];
        sX[i] = v;
        out[row0 * DIM + i] = v;
    }
    __syncthreads();

    const int ci = tid & 31;
    const int rg = tid >> 5;
    const float sq = sqrtf(0.01f);   // matches jnp.sqrt(DT) in fp32

    for (int step = 0; step < NSTEPS; ++step) {
        // ---- Drift layer 1: H = tanh(X @ Wd1 + bd1) ----
        layer1(sX, sWd1, sbd1, sH, rg, ci);
        __syncthreads();

        // ---- Drift layer 2: F = H @ Wd2 + bd2 ----
        {
            float acc[8][2];
#pragma unroll
            for (int r = 0; r < 8; r++) { acc[r][0] = 0.0f; acc[r][1] = 0.0f; }
#pragma unroll 8
            for (int k = 0; k < HID; k++) {
                float hv[8], wv[2];
#pragma unroll
                for (int r = 0; r < 8; r++) hv[r] = sH[(rg * 8 + r) * HID + k];
                wv[0] = sWd2[k * DIM + ci];
                wv[1] = sWd2[k * DIM + ci + 32];
#pragma unroll
                for (int r = 0; r < 8; r++) {
                    acc[r][0] = fmaf(hv[r], wv[0], acc[r][0]);
                    acc[r][1] = fmaf(hv[r], wv[1], acc[r][1]);
                }
            }
#pragma unroll
            for (int m = 0; m < 2; m++) {
                const int c = ci + 32 * m;
                const float b = sbd2[c];
#pragma unroll
                for (int r = 0; r < 8; r++)
                    sF[(rg * 8 + r) * DIM + c] = acc[r][m] + b;
            }
        }
        __syncthreads();

        // ---- Diffusion layer 1: H = tanh(X @ Wg1 + bg1) ----
        layer1(sX, sWg1, sbg1, sH, rg, ci);
        __syncthreads();

        // ---- Diffusion layer 2 + Euler-Maruyama update ----
        {
            // Prefetch noise for this thread's (row, col) tile early (global, coalesced)
            float dw[8][2];
            const size_t nbase = (size_t)step * BATCH * DIM;
#pragma unroll
            for (int m = 0; m < 2; m++) {
                const int c = ci + 32 * m;
#pragma unroll
                for (int r = 0; r < 8; r++)
                    dw[r][m] = noise[nbase + (size_t)(row0 + rg * 8 + r) * DIM + c];
            }

            float acc[8][2];
#pragma unroll
            for (int r = 0; r < 8; r++) { acc[r][0] = 0.0f; acc[r][1] = 0.0f; }
#pragma unroll 8
            for (int k = 0; k < HID; k++) {
                float hv[8], wv[2];
#pragma unroll
                for (int r = 0; r < 8; r++) hv[r] = sH[(rg * 8 + r) * HID + k];
                wv[0] = sWg2[k * DIM + ci];
                wv[1] = sWg2[k * DIM + ci + 32];
#pragma unroll
                for (int r = 0; r < 8; r++) {
                    acc[r][0] = fmaf(hv[r], wv[0], acc[r][0]);
                    acc[r][1] = fmaf(hv[r], wv[1], acc[r][1]);
                }
            }

            const size_t obase = (size_t)(step + 1) * BATCH * DIM;
#pragma unroll
            for (int m = 0; m < 2; m++) {
                const int c = ci + 32 * m;
                const float bg = sbg2[c];
#pragma unroll
                for (int r = 0; r < 8; r++) {
                    const int rl = rg * 8 + r;
                    const float g  = acc[r][m] + bg;
                    const float xn = sX[rl * DIM + c]
                                   + DT_F * sF[rl * DIM + c]
                                   + g * (dw[r][m] * sq);
                    sX[rl * DIM + c] = xn;
                    out[obase + (size_t)(row0 + rl) * DIM + c] = xn;
                }
            }
        }
        __syncthreads();
    }
}

extern "C" void kernel_launch(void* const* d_in, const int* in_sizes, int n_in,
                              void* d_out, int out_size)
{
    const float* x0    = (const float*)d_in[0];
    // d_in[1] = t_span (unused: DT fixed at 0.01)
    const float* noise = (const float*)d_in[2];
    const float* Wd1   = (const float*)d_in[3];
    const float* bd1   = (const float*)d_in[4];
    const float* Wd2   = (const float*)d_in[5];
    const float* bd2   = (const float*)d_in[6];
    const float* Wg1   = (const float*)d_in[7];
    const float* bg1   = (const float*)d_in[8];
    const float* Wg2   = (const float*)d_in[9];
    const float* bg2   = (const float*)d_in[10];
    float* out = (float*)d_out;

    const size_t smem_bytes = (size_t)SMEM_FLOATS * sizeof(float);  // 198,144 B
    cudaFuncSetAttribute(sde_persistent_kernel,
                         cudaFuncAttributeMaxDynamicSharedMemorySize,
                         (int)smem_bytes);

    sde_persistent_kernel<<<NCTA, NTHR, smem_bytes>>>(
        x0, noise, Wd1, bd1, Wd2, bd2, Wg1, bg1, Wg2, bg2, out);
}

// round 2
// speedup vs baseline: 1.2453x; 1.2453x over previous
#include <cuda_runtime.h>
#include <math.h>

#define DIM    64
#define HID    128
#define NSTEPS 100
#define BATCH  8192
#define RPC    64
#define NCTA   (BATCH / RPC)   // 128
#define NTHR   256
#define DT_F   0.01f

#define XT_STRIDE 68   // padded row stride for [DIM][RPC] transposed X
#define HT_STRIDE 68   // padded row stride for [HID][RPC] transposed H

// smem floats: 4 weight mats (8192 ea) + biases (384) + XT (64*68) + 2*HT (128*68 ea)
#define SMEM_FLOATS (4*8192 + 384 + 64*XT_STRIDE + 2*128*HT_STRIDE)  // 54,912 -> 219,648 B

// ---- packed fp32x2 helpers (sm_100+) ----
__device__ __forceinline__ void fma2(unsigned long long& acc, double a, unsigned long long b) {
    asm("fma.rn.f32x2 %0, %1, %2, %0;"
        : "+l"(acc) : "l"(__double_as_longlong(a)), "l"(b));
}
__device__ __forceinline__ unsigned long long dup2(float w) {
    unsigned long long r;
    asm("mov.b64 %0, {%1, %1};" : "=l"(r) : "f"(w));
    return r;
}
__device__ __forceinline__ float2 unpk(unsigned long long v) {
    float2 r;
    asm("mov.b64 {%0, %1}, %2;" : "=f"(r.x), "=f"(r.y) : "l"(v));
    return r;
}

// tanh(x) = 1 - 2/(exp(2x)+1), via MUFU EX2 + RCP. Abs err ~1e-7, branch-free,
// correct saturation at +/-inf.
__device__ __forceinline__ float fast_tanh(float x) {
    float e;
    asm("ex2.approx.f32 %0, %1;" : "=f"(e) : "f"(x * 2.8853900817779268f)); // 2*log2(e)
    float r;
    asm("rcp.approx.f32 %0, %1;" : "=f"(r) : "f"(e + 1.0f));
    return fmaf(-2.0f, r, 1.0f);
}

__global__ __launch_bounds__(NTHR, 1)
void sde_kernel(const float* __restrict__ x0,
                const float* __restrict__ noise,
                const float* __restrict__ Wd1, const float* __restrict__ bd1,
                const float* __restrict__ Wd2, const float* __restrict__ bd2,
                const float* __restrict__ Wg1, const float* __restrict__ bg1,
                const float* __restrict__ Wg2, const float* __restrict__ bg2,
                float* __restrict__ out)
{
    extern __shared__ float sm[];
    float* sWd1 = sm;                  // [64][128] k-major
    float* sWg1 = sWd1 + 8192;
    float* sWd2 = sWg1 + 8192;         // [128][64] k-major
    float* sWg2 = sWd2 + 8192;
    float* sbd1 = sWg2 + 8192;         // 128
    float* sbg1 = sbd1 + 128;          // 128
    float* sbd2 = sbg1 + 128;          // 64
    float* sbg2 = sbd2 + 64;           // 64
    float* sXT  = sbg2 + 64;           // [64][XT_STRIDE]  (x transposed: [k][row])
    float* sHd  = sXT + 64 * XT_STRIDE; // [128][HT_STRIDE] (drift hidden, transposed)
    float* sHg  = sHd + 128 * HT_STRIDE;

    const int tid  = threadIdx.x;
    const int ci   = tid & 31;
    const int rg   = tid >> 5;
    const int row0 = blockIdx.x * RPC;
    const int rbase = rg * 8;

    // ---- stage weights/biases; scatter x0 into transposed layout; emit out[0] ----
    for (int i = tid; i < 8192; i += NTHR) {
        sWd1[i] = Wd1[i]; sWg1[i] = Wg1[i]; sWd2[i] = Wd2[i]; sWg2[i] = Wg2[i];
    }
    for (int i = tid; i < 128; i += NTHR) { sbd1[i] = bd1[i]; sbg1[i] = bg1[i]; }
    for (int i = tid; i < 64;  i += NTHR) { sbd2[i] = bd2[i]; sbg2[i] = bg2[i]; }
    for (int i = tid; i < RPC * DIM; i += NTHR) {
        float v = x0[row0 * DIM + i];
        out[row0 * DIM + i] = v;
        int r = i >> 6, c = i & 63;
        sXT[c * XT_STRIDE + r] = v;
    }
    __syncthreads();

    const float sq = sqrtf(0.01f);

    for (int step = 0; step < NSTEPS; ++step) {
        // ================= fused layer 1 (drift + diffusion) =================
        // H?[c][row] = tanh( sum_k X[row][k] * W?1[k][c] + b?1[c] )
        unsigned long long ad[4][4], ag[4][4];
#pragma unroll
        for (int p = 0; p < 4; p++)
#pragma unroll
            for (int m = 0; m < 4; m++) { ad[p][m] = 0ull; ag[p][m] = 0ull; }

#pragma unroll 4
        for (int k = 0; k < DIM; k++) {
            // two LDS.128 broadcasts cover this thread's 8 rows (4 fp32x2 pairs)
            double2 xa = *reinterpret_cast<const double2*>(&sXT[k * XT_STRIDE + rbase]);
            double2 xb = *reinterpret_cast<const double2*>(&sXT[k * XT_STRIDE + rbase + 4]);
            const float* wd = &sWd1[k * HID + ci];
            const float* wg = &sWg1[k * HID + ci];
#pragma unroll
            for (int m = 0; m < 4; m++) {
                unsigned long long wpd = dup2(wd[32 * m]);
                unsigned long long wpg = dup2(wg[32 * m]);
                fma2(ad[0][m], xa.x, wpd); fma2(ad[1][m], xa.y, wpd);
                fma2(ad[2][m], xb.x, wpd); fma2(ad[3][m], xb.y, wpd);
                fma2(ag[0][m], xa.x, wpg); fma2(ag[1][m], xa.y, wpg);
                fma2(ag[2][m], xb.x, wpg); fma2(ag[3][m], xb.y, wpg);
            }
        }

        // bias + tanh + store H (pairs, STS.64)
#pragma unroll
        for (int m = 0; m < 4; m++) {
            const int c = ci + 32 * m;
            const float b1d = sbd1[c];
            const float b1g = sbg1[c];
#pragma unroll
            for (int p = 0; p < 4; p++) {
                float2 vd = unpk(ad[p][m]);
                float2 vg = unpk(ag[p][m]);
                float2 hd = make_float2(fast_tanh(vd.x + b1d), fast_tanh(vd.y + b1d));
                float2 hg = make_float2(fast_tanh(vg.x + b1g), fast_tanh(vg.y + b1g));
                *reinterpret_cast<float2*>(&sHd[c * HT_STRIDE + rbase + 2 * p]) = hd;
                *reinterpret_cast<float2*>(&sHg[c * HT_STRIDE + rbase + 2 * p]) = hg;
            }
        }
        __syncwarp();   // rows are warp-private; lane-crossing only within warp

        // ================= fused layer 2 + Euler-Maruyama update =================
        unsigned long long fa[4][2], ga[4][2];
#pragma unroll
        for (int p = 0; p < 4; p++)
#pragma unroll
            for (int m = 0; m < 2; m++) { fa[p][m] = 0ull; ga[p][m] = 0ull; }

        // prefetch this thread's noise tile (coalesced LDG, hides DRAM latency)
        float dw[4][2][2];
        const size_t nbase = (size_t)step * BATCH * DIM;
#pragma unroll
        for (int m = 0; m < 2; m++) {
            const int c = ci + 32 * m;
#pragma unroll
            for (int p = 0; p < 4; p++) {
                dw[p][m][0] = noise[nbase + (size_t)(row0 + rbase + 2 * p)     * DIM + c];
                dw[p][m][1] = noise[nbase + (size_t)(row0 + rbase + 2 * p + 1) * DIM + c];
            }
        }

#pragma unroll 4
        for (int k = 0; k < HID; k++) {
            double2 hda = *reinterpret_cast<const double2*>(&sHd[k * HT_STRIDE + rbase]);
            double2 hdb = *reinterpret_cast<const double2*>(&sHd[k * HT_STRIDE + rbase + 4]);
            double2 hga = *reinterpret_cast<const double2*>(&sHg[k * HT_STRIDE + rbase]);
            double2 hgb = *reinterpret_cast<const double2*>(&sHg[k * HT_STRIDE + rbase + 4]);
#pragma unroll
            for (int m = 0; m < 2; m++) {
                unsigned long long wpd = dup2(sWd2[k * DIM + ci + 32 * m]);
                unsigned long long wpg = dup2(sWg2[k * DIM + ci + 32 * m]);
                fma2(fa[0][m], hda.x, wpd); fma2(fa[1][m], hda.y, wpd);
                fma2(fa[2][m], hdb.x, wpd); fma2(fa[3][m], hdb.y, wpd);
                fma2(ga[0][m], hga.x, wpg); fma2(ga[1][m], hga.y, wpg);
                fma2(ga[2][m], hgb.x, wpg); fma2(ga[3][m], hgb.y, wpg);
            }
        }

        const size_t obase = (size_t)(step + 1) * BATCH * DIM;
#pragma unroll
        for (int m = 0; m < 2; m++) {
            const int c = ci + 32 * m;
            const float b2d = sbd2[c];
            const float b2g = sbg2[c];
#pragma unroll
            for (int p = 0; p < 4; p++) {
                float2 fv = unpk(fa[p][m]);
                float2 gv = unpk(ga[p][m]);
                float2 xo = *reinterpret_cast<const float2*>(&sXT[c * XT_STRIDE + rbase + 2 * p]);
                const float f0 = fv.x + b2d, f1 = fv.y + b2d;
                const float g0 = gv.x + b2g, g1 = gv.y + b2g;
                const float xn0 = xo.x + f0 * DT_F + g0 * (dw[p][m][0] * sq);
                const float xn1 = xo.y + f1 * DT_F + g1 * (dw[p][m][1] * sq);
                *reinterpret_cast<float2*>(&sXT[c * XT_STRIDE + rbase + 2 * p]) = make_float2(xn0, xn1);
                out[obase + (size_t)(row0 + rbase + 2 * p)     * DIM + c] = xn0;
                out[obase + (size_t)(row0 + rbase + 2 * p + 1) * DIM + c] = xn1;
            }
        }
        __syncwarp();
    }
}

extern "C" void kernel_launch(void* const* d_in, const int* in_sizes, int n_in,
                              void* d_out, int out_size)
{
    const float* x0    = (const float*)d_in[0];
    // d_in[1] = t_span (unused; dt fixed)
    const float* noise = (const float*)d_in[2];
    const float* Wd1   = (const float*)d_in[3];
    const float* bd1   = (const float*)d_in[4];
    const float* Wd2   = (const float*)d_in[5];
    const float* bd2   = (const float*)d_in[6];
    const float* Wg1   = (const float*)d_in[7];
    const float* bg1   = (const float*)d_in[8];
    const float* Wg2   = (const float*)d_in[9];
    const float* bg2   = (const float*)d_in[10];
    float* out = (float*)d_out;

    const size_t smem_bytes = (size_t)SMEM_FLOATS * sizeof(float);  // 219,648 B
    cudaFuncSetAttribute(sde_kernel,
                         cudaFuncAttributeMaxDynamicSharedMemorySize,
                         (int)smem_bytes);

    sde_kernel<<<NCTA, NTHR, smem_bytes>>>(
        x0, noise, Wd1, bd1, Wd2, bd2, Wg1, bg1, Wg2, bg2, out);
}